// round 12
// baseline (speedup 1.0000x reference)
#include <cuda_runtime.h>
#include <cstdint>

// Problem constants
#define Bb 2
#define Ss 2048
#define Dd 512
#define Hh 8
#define DHd 64
#define BSr (Bb*Ss)     // 4096 rows

// ---------------------------------------------------------------------------
// Pre-split bf16 hi/lo device buffers (u32 = bf16x2 word for an element pair).
//   g_Xbf/g_Wbf/g_Wobf/g_Obf: [row][512]  -> hi words [0:256), lo words [256:512)
//   g_Qbf/g_Kbf/g_Vbf: [(h*Bb+b)*Ss + s][64] -> hi words [0:32), lo [32:64)
// ---------------------------------------------------------------------------
__device__ __align__(16) uint32_t g_Xbf [4096*512];
__device__ __align__(16) uint32_t g_Wbf [1536*512];
__device__ __align__(16) uint32_t g_Wobf[512*512];
__device__ __align__(16) uint32_t g_Obf [4096*512];
__device__ __align__(16) uint32_t g_Qbf [Hh*Bb*Ss*64];
__device__ __align__(16) uint32_t g_Kbf [Hh*Bb*Ss*64];
__device__ __align__(16) uint32_t g_Vbf [Hh*Bb*Ss*64];

// ---------------------------------------------------------------------------
// helpers
// ---------------------------------------------------------------------------
__device__ __forceinline__ void mma_bf16(float* d, const uint32_t* a,
                                         uint32_t b0, uint32_t b1) {
    asm volatile("mma.sync.aligned.m16n8k16.row.col.f32.bf16.bf16.f32 "
                 "{%0,%1,%2,%3}, {%4,%5,%6,%7}, {%8,%9}, {%0,%1,%2,%3};"
                 : "+f"(d[0]), "+f"(d[1]), "+f"(d[2]), "+f"(d[3])
                 : "r"(a[0]), "r"(a[1]), "r"(a[2]), "r"(a[3]), "r"(b0), "r"(b1));
}
__device__ __forceinline__ void ldsm4(uint32_t* r, uint32_t a) {
    asm volatile("ldmatrix.sync.aligned.m8n8.x4.shared.b16 {%0,%1,%2,%3}, [%4];"
                 : "=r"(r[0]), "=r"(r[1]), "=r"(r[2]), "=r"(r[3]) : "r"(a));
}
__device__ __forceinline__ void ldsm4t(uint32_t* r, uint32_t a) {
    asm volatile("ldmatrix.sync.aligned.m8n8.x4.trans.shared.b16 {%0,%1,%2,%3}, [%4];"
                 : "=r"(r[0]), "=r"(r[1]), "=r"(r[2]), "=r"(r[3]) : "r"(a));
}
__device__ __forceinline__ uint32_t smem_u32(const void* p) {
    uint32_t a;
    asm("{ .reg .u64 t; cvta.to.shared.u64 t, %1; cvt.u32.u64 %0, t; }"
        : "=r"(a) : "l"(p));
    return a;
}
__device__ __forceinline__ uint32_t bf2(float hi, float lo) {
    uint32_t r;
    asm("cvt.rn.bf16x2.f32 %0, %1, %2;" : "=r"(r) : "f"(hi), "f"(lo));
    return r;
}
__device__ __forceinline__ float bflo_f(uint32_t w) { return __uint_as_float(w << 16); }
__device__ __forceinline__ float bfhi_f(uint32_t w) { return __uint_as_float(w & 0xFFFF0000u); }
__device__ __forceinline__ void split2(float2 f, uint32_t& whi, uint32_t& wlo) {
    whi = bf2(f.y, f.x);
    float rx = f.x - bflo_f(whi);
    float ry = f.y - bfhi_f(whi);
    wlo = bf2(ry, rx);
}
__device__ __forceinline__ void cpa16(uint32_t dst, const uint32_t* src) {
    asm volatile("cp.async.cg.shared.global [%0], [%1], 16;"
                 :: "r"(dst), "l"(src) : "memory");
}
#define CP_COMMIT() asm volatile("cp.async.commit_group;" ::: "memory")
#define CP_WAIT0()  asm volatile("cp.async.wait_group 0;" ::: "memory")
#define CP_WAIT1()  asm volatile("cp.async.wait_group 1;" ::: "memory")

// ---------------------------------------------------------------------------
// Kernel 0: pre-split X, W, Wo into bf16 hi/lo buffers (runs once)
// ---------------------------------------------------------------------------
__global__ void presplit(const float* __restrict__ X,
                         const float* __restrict__ W,
                         const float* __restrict__ Wo) {
    for (int idx = blockIdx.x * blockDim.x + threadIdx.x;
         idx < 1572864; idx += gridDim.x * blockDim.x) {
        const float* src; uint32_t* dst; int p;
        if (idx < 1048576)      { p = idx;           src = X;  dst = g_Xbf; }
        else if (idx < 1441792) { p = idx - 1048576; src = W;  dst = g_Wbf; }
        else                    { p = idx - 1441792; src = Wo; dst = g_Wobf; }
        int row = p >> 8, wc = p & 255;
        float2 f = *(const float2*)&src[(size_t)row * 512 + wc * 2];
        uint32_t hi, lo; split2(f, hi, lo);
        dst[(size_t)row * 512 + wc]       = hi;
        dst[(size_t)row * 512 + 256 + wc] = lo;
    }
}

// ---------------------------------------------------------------------------
// Unified bf16x3 GEMM, 2-stage cp.async pipeline. C = A @ B^T + bias, K=512.
// CTA tile 128x128, 8 warps 2(M) x 4(N). K chunks of 32 elements (16 words),
// row stride 80B (conflict-free ldmatrix). 3 passes: Ah*Bh + Ah*Bl + Al*Bh.
// MODE 0: A=g_Xbf, B=g_Wbf, scatter to g_Qbf/g_Kbf/g_Vbf (pre-split).
// MODE 1: A=g_Obf, B=g_Wobf, write fp32 out.
// ---------------------------------------------------------------------------
#define GSTR2 80
#define GSTAGE 40960          // Ahi 10240 | Alo 10240 | Bhi 10240 | Blo 10240
#define GEMM_SMEM 81920

template<int MODE>
__global__ __launch_bounds__(256, 2) void tc_gemm(const float* __restrict__ bias,
                                                  float* __restrict__ out) {
    extern __shared__ char smg[];
    const uint32_t sb = smem_u32(smg);
    const int tid = threadIdx.x;
    const int lane = tid & 31;
    const int w = tid >> 5;
    const int g = lane >> 2;
    const int tg = lane & 3;
    const int r8 = lane & 7;
    const int mlo = (lane >> 3) & 1;
    const int mhi = lane >> 4;
    const int bm = blockIdx.y * 128;
    const int bn = blockIdx.x * 128;

    const uint32_t* Aw = (MODE == 0) ? g_Xbf : g_Obf;
    const uint32_t* Bw = (MODE == 0) ? g_Wbf : g_Wobf;

    const int wm = (w >> 2) * 64;
    const int wn = (w & 3) * 32;

    float acc[4][4][4];
#pragma unroll
    for (int mb = 0; mb < 4; mb++)
#pragma unroll
        for (int nb = 0; nb < 4; nb++)
#pragma unroll
            for (int q = 0; q < 4; q++) acc[mb][nb][q] = 0.f;

    const uint32_t aA = sb + (uint32_t)((wm + mlo * 8 + r8) * GSTR2 + mhi * 16);
    const uint32_t aB = sb + 20480 + (uint32_t)((wn + mhi * 8 + r8) * GSTR2 + mlo * 16);

    // staging lambda: chunk c (16 words of hi + 16 of lo per row) into stage s
    auto stage_chunk = [&](int c, int s) {
        const int c0w = c * 16;
#pragma unroll
        for (int it = 0; it < 8; it++) {
            int item = tid + it * 256;
            int side = item >> 10;          // 0 = A, 1 = B
            int idx = item & 1023;
            int row = idx >> 3;             // 0..127
            int q = idx & 7;
            int half = q >> 2;              // 0 hi, 1 lo
            int c4 = q & 3;                 // uint4 within row
            const uint32_t* src = (side ? Bw + (size_t)(bn + row) * 512
                                        : Aw + (size_t)(bm + row) * 512)
                                  + (half << 8) + c0w + c4 * 4;
            uint32_t dst = sb + s * GSTAGE + side * 20480 + half * 10240
                         + (uint32_t)(row * GSTR2 + c4 * 16);
            cpa16(dst, src);
        }
    };

    stage_chunk(0, 0);
    CP_COMMIT();

#pragma unroll 1
    for (int c = 0; c < 16; c++) {
        const int s = c & 1;
        if (c + 1 < 16) {
            stage_chunk(c + 1, s ^ 1);
            CP_COMMIT();
            CP_WAIT1();
        } else {
            CP_WAIT0();
        }
        __syncthreads();

        const uint32_t so = s * GSTAGE;
#pragma unroll
        for (int kk = 0; kk < 2; kk++) {
            uint32_t ah[4][4], al[4][4];
#pragma unroll
            for (int mb = 0; mb < 4; mb++) {
                ldsm4(ah[mb], aA + so + mb * (16 * GSTR2) + kk * 32);
                ldsm4(al[mb], aA + so + 10240 + mb * (16 * GSTR2) + kk * 32);
            }
#pragma unroll
            for (int j = 0; j < 2; j++) {
                uint32_t bh[4], bl[4];
                ldsm4(bh, aB + so + j * (16 * GSTR2) + kk * 32);
                ldsm4(bl, aB + so + 10240 + j * (16 * GSTR2) + kk * 32);
#pragma unroll
                for (int mb = 0; mb < 4; mb++) {
                    mma_bf16(acc[mb][2*j],   ah[mb], bh[0], bh[1]);
                    mma_bf16(acc[mb][2*j+1], ah[mb], bh[2], bh[3]);
                    mma_bf16(acc[mb][2*j],   ah[mb], bl[0], bl[1]);
                    mma_bf16(acc[mb][2*j+1], ah[mb], bl[2], bl[3]);
                    mma_bf16(acc[mb][2*j],   al[mb], bh[0], bh[1]);
                    mma_bf16(acc[mb][2*j+1], al[mb], bh[2], bh[3]);
                }
            }
        }
        __syncthreads();   // all warps done with stage s before it is restaged
    }

    // ---- epilogue ----
#pragma unroll
    for (int nb = 0; nb < 4; nb++) {
        if (MODE == 0) {
            const int nbb = bn + wn + nb * 8;
            const int h = nbb / 192;
            const int r = nbb - h * 192;
            const int t = r >> 6;
            uint32_t* dst = (t == 0) ? g_Qbf : (t == 1) ? g_Kbf : g_Vbf;
            const int wc = ((r & 63) >> 1) + tg;
            const float2 bia = *(const float2*)&bias[nbb + 2 * tg];
#pragma unroll
            for (int mb = 0; mb < 4; mb++) {
                const int m0 = bm + wm + mb * 16 + g;
                {
                    const int bi = m0 >> 11, ss = m0 & 2047;
                    const size_t base = ((size_t)(h * Bb + bi) * Ss + ss) * 64;
                    uint32_t hi, lo;
                    split2(make_float2(acc[mb][nb][0] + bia.x,
                                       acc[mb][nb][1] + bia.y), hi, lo);
                    dst[base + wc] = hi;
                    dst[base + 32 + wc] = lo;
                }
                {
                    const int m1 = m0 + 8;
                    const int bi = m1 >> 11, ss = m1 & 2047;
                    const size_t base = ((size_t)(h * Bb + bi) * Ss + ss) * 64;
                    uint32_t hi, lo;
                    split2(make_float2(acc[mb][nb][2] + bia.x,
                                       acc[mb][nb][3] + bia.y), hi, lo);
                    dst[base + wc] = hi;
                    dst[base + 32 + wc] = lo;
                }
            }
        } else {
            const int n0 = bn + wn + nb * 8 + 2 * tg;
            const float2 bia = *(const float2*)&bias[n0];
#pragma unroll
            for (int mb = 0; mb < 4; mb++) {
                const int m0 = bm + wm + mb * 16 + g;
                float2 v0; v0.x = acc[mb][nb][0] + bia.x; v0.y = acc[mb][nb][1] + bia.y;
                float2 v1; v1.x = acc[mb][nb][2] + bia.x; v1.y = acc[mb][nb][3] + bia.y;
                *(float2*)&out[(size_t)m0 * 512 + n0] = v0;
                *(float2*)&out[(size_t)(m0 + 8) * 512 + n0] = v1;
            }
        }
    }
}

// ---------------------------------------------------------------------------
// Kernel 2: flash attention, bf16x3 mma, 2-stage cp.async K/V pipeline.
// smem: KV stage0 [0,36864) | KV stage1 [36864,73728) | Q [73728,110592)
// per stage: Khi 9216 | Klo 9216 | Vhi 9216 | Vlo 9216 (row stride 144B)
// grid = (H, S/128, B): h fastest -> shift/mask L2 reuse across heads.
// ---------------------------------------------------------------------------
#define RSTR 144
#define KVSTAGE 36864
#define AOF_Q 73728
#define ATT_SMEM 110592

__global__ __launch_bounds__(256, 2) void attn_kernel(const float* __restrict__ shift,
                                                      const float* __restrict__ mask) {
    extern __shared__ char smc[];
    const uint32_t sb = smem_u32(smc);

    const int h  = blockIdx.x;
    const int qt = blockIdx.y;
    const int b  = blockIdx.z;
    const int tid = threadIdx.x;
    const int lane = tid & 31;
    const int w = tid >> 5;
    const int g = lane >> 2;
    const int tg = lane & 3;
    const int r8 = lane & 7;
    const int mlo = (lane >> 3) & 1;
    const int mhi = lane >> 4;

    const float c1  = 0.125f * 1.4426950408889634f;            // log2e / sqrt(64)
    const float hs2 = exp2f(-(float)h) * 1.4426950408889634f;  // head_scale * log2e

    const uint32_t* Qw = g_Qbf + ((size_t)(h * Bb + b) * Ss + qt * 128) * 64;
    const uint32_t* Kw = g_Kbf + ((size_t)(h * Bb + b) * Ss) * 64;
    const uint32_t* Vw = g_Vbf + ((size_t)(h * Bb + b) * Ss) * 64;

    // ---- stage Q once (2048 uint4 = 8 cp.async/thread) ----
#pragma unroll
    for (int it = 0; it < 8; it++) {
        int item = tid + it * 256;
        int row = item >> 4, c4 = item & 15;
        int hi = c4 >> 3;
        cpa16(sb + AOF_Q + hi * 18432 + (uint32_t)(row * RSTR + (c4 & 7) * 16),
              Qw + row * 64 + c4 * 4);
    }
    CP_COMMIT();

    // staging lambda: K/V tile kt into stage s
    auto stage_kv = [&](int kt, int s) {
#pragma unroll
        for (int it = 0; it < 8; it++) {
            int item = tid + it * 256;
            int side = item >> 10;          // 0 = K, 1 = V
            int idx = item & 1023;
            int row = idx >> 4, c4 = idx & 15;
            int hi = c4 >> 3;
            const uint32_t* src = (side ? Vw : Kw) + kt * 4096 + row * 64 + c4 * 4;
            cpa16(sb + s * KVSTAGE + side * 18432 + hi * 9216
                     + (uint32_t)(row * RSTR + (c4 & 7) * 16), src);
        }
    };

    stage_kv(0, 0);
    CP_COMMIT();

    const uint32_t aQ = sb + AOF_Q + (uint32_t)((w * 16 + mlo * 8 + r8) * RSTR + mhi * 16);
    const uint32_t aKb = sb + (uint32_t)((mhi * 8 + r8) * RSTR + mlo * 16);
    const uint32_t aVb = sb + 18432 + (uint32_t)((mlo * 8 + r8) * RSTR + mhi * 16);

    float oacc[8][4];
#pragma unroll
    for (int nb = 0; nb < 8; nb++)
#pragma unroll
        for (int q = 0; q < 4; q++) oacc[nb][q] = 0.f;
    float ls0 = 0.f, ls1 = 0.f;

    const int q0 = qt * 128 + w * 16 + g;
    const float* shp = shift + ((size_t)b * Ss + q0) * Ss + 2 * tg;
    const float* mkp = mask  + ((size_t)b * Ss + q0) * Ss + 2 * tg;

#pragma unroll 1
    for (int kt = 0; kt < 32; kt++) {
        const int s = kt & 1;
        if (kt + 1 < 32) {
            stage_kv(kt + 1, s ^ 1);
            CP_COMMIT();
            CP_WAIT1();
        } else {
            CP_WAIT0();
        }
        __syncthreads();

        const uint32_t aK = aKb + s * KVSTAGE;
        const uint32_t aV = aVb + s * KVSTAGE;

        // ---- S = Q @ K^T (bf16 x3) ----
        float sacc[8][4];
#pragma unroll
        for (int nb = 0; nb < 8; nb++)
#pragma unroll
            for (int q = 0; q < 4; q++) sacc[nb][q] = 0.f;
#pragma unroll
        for (int kk = 0; kk < 4; kk++) {
            uint32_t qh[4], ql[4], kf[4];
            ldsm4(qh, aQ + kk * 32);
            ldsm4(ql, aQ + 18432 + kk * 32);
#pragma unroll
            for (int nbp = 0; nbp < 4; nbp++) {
                ldsm4(kf, aK + nbp * (16 * RSTR) + kk * 32);
                mma_bf16(sacc[2*nbp],   qh, kf[0], kf[1]);
                mma_bf16(sacc[2*nbp+1], qh, kf[2], kf[3]);
                mma_bf16(sacc[2*nbp],   ql, kf[0], kf[1]);
                mma_bf16(sacc[2*nbp+1], ql, kf[2], kf[3]);
                ldsm4(kf, aK + 9216 + nbp * (16 * RSTR) + kk * 32);
                mma_bf16(sacc[2*nbp],   qh, kf[0], kf[1]);
                mma_bf16(sacc[2*nbp+1], qh, kf[2], kf[3]);
            }
        }

        // ---- softmax in registers -> P fragments (hi/lo bf16) ----
        uint32_t pah[4][4], pal[4][4];
        const float* sh_r = shp + kt * 64;
        const float* mk_r = mkp + kt * 64;
#pragma unroll
        for (int nb = 0; nb < 8; nb++) {
            float2 sh0 = *(const float2*)(sh_r + nb * 8);
            float2 mk0 = *(const float2*)(mk_r + nb * 8);
            float2 sh1 = *(const float2*)(sh_r + 8 * Ss + nb * 8);
            float2 mk1 = *(const float2*)(mk_r + 8 * Ss + nb * 8);
            float t00 = fmaf(sacc[nb][0], c1, -hs2 * sh0.x);
            float t01 = fmaf(sacc[nb][1], c1, -hs2 * sh0.y);
            float t10 = fmaf(sacc[nb][2], c1, -hs2 * sh1.x);
            float t11 = fmaf(sacc[nb][3], c1, -hs2 * sh1.y);
            float p00 = exp2f(t00) * mk0.x;
            float p01 = exp2f(t01) * mk0.y;
            float p10 = exp2f(t10) * mk1.x;
            float p11 = exp2f(t11) * mk1.y;
            ls0 += p00 + p01;
            ls1 += p10 + p11;
            uint32_t w0 = bf2(p01, p00);
            uint32_t w1 = bf2(p11, p10);
            uint32_t w0l = bf2(p01 - bfhi_f(w0), p00 - bflo_f(w0));
            uint32_t w1l = bf2(p11 - bfhi_f(w1), p10 - bflo_f(w1));
            const int kk2 = nb >> 1;
            if (nb & 1) { pah[kk2][2] = w0; pah[kk2][3] = w1; pal[kk2][2] = w0l; pal[kk2][3] = w1l; }
            else        { pah[kk2][0] = w0; pah[kk2][1] = w1; pal[kk2][0] = w0l; pal[kk2][1] = w1l; }
        }

        // ---- O += P @ V (bf16 x3, V via ldmatrix.trans) ----
#pragma unroll
        for (int kk2 = 0; kk2 < 4; kk2++) {
#pragma unroll
            for (int nbp = 0; nbp < 4; nbp++) {
                uint32_t vf[4];
                ldsm4t(vf, aV + kk2 * (16 * RSTR) + nbp * 32);
                mma_bf16(oacc[2*nbp],   pah[kk2], vf[0], vf[1]);
                mma_bf16(oacc[2*nbp+1], pah[kk2], vf[2], vf[3]);
                mma_bf16(oacc[2*nbp],   pal[kk2], vf[0], vf[1]);
                mma_bf16(oacc[2*nbp+1], pal[kk2], vf[2], vf[3]);
                ldsm4t(vf, aV + 9216 + kk2 * (16 * RSTR) + nbp * 32);
                mma_bf16(oacc[2*nbp],   pah[kk2], vf[0], vf[1]);
                mma_bf16(oacc[2*nbp+1], pah[kk2], vf[2], vf[3]);
            }
        }
        __syncthreads();   // all warps done with stage s before restage
    }

    // ---- epilogue: reduce row sums, scale, write pre-split O ----
    ls0 += __shfl_xor_sync(0xffffffffu, ls0, 1);
    ls0 += __shfl_xor_sync(0xffffffffu, ls0, 2);
    ls1 += __shfl_xor_sync(0xffffffffu, ls1, 1);
    ls1 += __shfl_xor_sync(0xffffffffu, ls1, 2);
    const float i0 = 1.f / ls0;
    const float i1 = 1.f / ls1;

    const size_t base0 = ((size_t)b * Ss + q0) * 512 + h * 32 + tg;
#pragma unroll
    for (int nb = 0; nb < 8; nb++) {
        uint32_t hi, lo;
        split2(make_float2(oacc[nb][0] * i0, oacc[nb][1] * i0), hi, lo);
        g_Obf[base0 + nb * 4] = hi;
        g_Obf[base0 + 256 + nb * 4] = lo;
        split2(make_float2(oacc[nb][2] * i1, oacc[nb][3] * i1), hi, lo);
        g_Obf[base0 + 8 * 512 + nb * 4] = hi;
        g_Obf[base0 + 8 * 512 + 256 + nb * 4] = lo;
    }
}

// ---------------------------------------------------------------------------
extern "C" void kernel_launch(void* const* d_in, const int* in_sizes, int n_in,
                              void* d_out, int out_size) {
    const float* x     = (const float*)d_in[0];
    const float* shift = (const float*)d_in[1];
    const float* mask  = (const float*)d_in[2];
    const float* W     = (const float*)d_in[3];
    const float* b     = (const float*)d_in[4];
    const float* Wo    = (const float*)d_in[5];
    const float* bo    = (const float*)d_in[6];
    float* out = (float*)d_out;

    cudaFuncSetAttribute(tc_gemm<0>, cudaFuncAttributeMaxDynamicSharedMemorySize,
                         GEMM_SMEM);
    cudaFuncSetAttribute(tc_gemm<1>, cudaFuncAttributeMaxDynamicSharedMemorySize,
                         GEMM_SMEM);
    cudaFuncSetAttribute(attn_kernel, cudaFuncAttributeMaxDynamicSharedMemorySize,
                         ATT_SMEM);

    // split X/W/Wo once
    presplit<<<2048, 256>>>(x, W, Wo);

    // QKV projection: M=4096, N=1536, K=512 (bf16x3, pipelined)
    tc_gemm<0><<<dim3(12, 32), 256, GEMM_SMEM>>>(b, nullptr);

    // attention: 128q x 64k tiles (bf16x3, pipelined K/V)
    attn_kernel<<<dim3(Hh, Ss / 128, Bb), 256, ATT_SMEM>>>(shift, mask);

    // output projection: M=4096, N=512, K=512 (bf16x3, pipelined)
    tc_gemm<1><<<dim3(4, 32), 256, GEMM_SMEM>>>(bo, out);
}

// round 13
// speedup vs baseline: 1.1795x; 1.1795x over previous
#include <cuda_runtime.h>
#include <cuda_fp16.h>
#include <cstdint>

// Problem constants
#define Bb 2
#define Ss 2048
#define Dd 512
#define Hh 8
#define DHd 64
#define BSr (Bb*Ss)     // 4096 rows

// ---------------------------------------------------------------------------
// Global scratch.
//   bf16 hi/lo (u32 = bf16x2): g_Xbf/g_Wbf/g_Wobf/g_Obf [row][512]:
//        hi words [0:256), lo words [256:512)
//   fp16 (u32 = f16x2): Q hi/lo, K single, V hi/lo; [(h*Bb+b)*Ss+s][32] words
// ---------------------------------------------------------------------------
__device__ __align__(16) uint32_t g_Xbf [4096*512];
__device__ __align__(16) uint32_t g_Wbf [1536*512];
__device__ __align__(16) uint32_t g_Wobf[512*512];
__device__ __align__(16) uint32_t g_Obf [4096*512];
__device__ __align__(16) uint32_t g_Qh16[Hh*Bb*Ss*32];
__device__ __align__(16) uint32_t g_Ql16[Hh*Bb*Ss*32];
__device__ __align__(16) uint32_t g_K16 [Hh*Bb*Ss*32];
__device__ __align__(16) uint32_t g_Vh16[Hh*Bb*Ss*32];
__device__ __align__(16) uint32_t g_Vl16[Hh*Bb*Ss*32];

// ---------------------------------------------------------------------------
// helpers
// ---------------------------------------------------------------------------
__device__ __forceinline__ void mma_bf16(float* d, const uint32_t* a,
                                         uint32_t b0, uint32_t b1) {
    asm volatile("mma.sync.aligned.m16n8k16.row.col.f32.bf16.bf16.f32 "
                 "{%0,%1,%2,%3}, {%4,%5,%6,%7}, {%8,%9}, {%0,%1,%2,%3};"
                 : "+f"(d[0]), "+f"(d[1]), "+f"(d[2]), "+f"(d[3])
                 : "r"(a[0]), "r"(a[1]), "r"(a[2]), "r"(a[3]), "r"(b0), "r"(b1));
}
__device__ __forceinline__ void mma_f16(float* d, const uint32_t* a,
                                        uint32_t b0, uint32_t b1) {
    asm volatile("mma.sync.aligned.m16n8k16.row.col.f32.f16.f16.f32 "
                 "{%0,%1,%2,%3}, {%4,%5,%6,%7}, {%8,%9}, {%0,%1,%2,%3};"
                 : "+f"(d[0]), "+f"(d[1]), "+f"(d[2]), "+f"(d[3])
                 : "r"(a[0]), "r"(a[1]), "r"(a[2]), "r"(a[3]), "r"(b0), "r"(b1));
}
__device__ __forceinline__ void ldsm4(uint32_t* r, uint32_t a) {
    asm volatile("ldmatrix.sync.aligned.m8n8.x4.shared.b16 {%0,%1,%2,%3}, [%4];"
                 : "=r"(r[0]), "=r"(r[1]), "=r"(r[2]), "=r"(r[3]) : "r"(a));
}
__device__ __forceinline__ void ldsm4t(uint32_t* r, uint32_t a) {
    asm volatile("ldmatrix.sync.aligned.m8n8.x4.trans.shared.b16 {%0,%1,%2,%3}, [%4];"
                 : "=r"(r[0]), "=r"(r[1]), "=r"(r[2]), "=r"(r[3]) : "r"(a));
}
__device__ __forceinline__ uint32_t smem_u32(const void* p) {
    uint32_t a;
    asm("{ .reg .u64 t; cvta.to.shared.u64 t, %1; cvt.u32.u64 %0, t; }"
        : "=r"(a) : "l"(p));
    return a;
}
// bf16 split helpers
__device__ __forceinline__ uint32_t bf2(float hi, float lo) {
    uint32_t r;
    asm("cvt.rn.bf16x2.f32 %0, %1, %2;" : "=r"(r) : "f"(hi), "f"(lo));
    return r;
}
__device__ __forceinline__ float bflo_f(uint32_t w) { return __uint_as_float(w << 16); }
__device__ __forceinline__ float bfhi_f(uint32_t w) { return __uint_as_float(w & 0xFFFF0000u); }
__device__ __forceinline__ void split2(float2 f, uint32_t& whi, uint32_t& wlo) {
    whi = bf2(f.y, f.x);
    float rx = f.x - bflo_f(whi);
    float ry = f.y - bfhi_f(whi);
    wlo = bf2(ry, rx);
}
// fp16 helpers: word = f16x2, x -> low half, y -> high half
__device__ __forceinline__ uint32_t pkh2(float x, float y) {
    __half2 h = __floats2half2_rn(x, y);
    return *(uint32_t*)&h;
}
__device__ __forceinline__ void splith2(float2 f, uint32_t& whi, uint32_t& wlo) {
    __half2 h = __floats2half2_rn(f.x, f.y);
    whi = *(uint32_t*)&h;
    float2 bk = __half22float2(h);
    __half2 l = __floats2half2_rn(f.x - bk.x, f.y - bk.y);
    wlo = *(uint32_t*)&l;
}
__device__ __forceinline__ void cpa16(uint32_t dst, const uint32_t* src) {
    asm volatile("cp.async.cg.shared.global [%0], [%1], 16;"
                 :: "r"(dst), "l"(src) : "memory");
}
#define CP_COMMIT() asm volatile("cp.async.commit_group;" ::: "memory")
#define CP_WAIT0()  asm volatile("cp.async.wait_group 0;" ::: "memory")
#define CP_WAIT1()  asm volatile("cp.async.wait_group 1;" ::: "memory")

// ---------------------------------------------------------------------------
// Kernel 0: pre-split X, W, Wo into bf16 hi/lo buffers (runs once)
// ---------------------------------------------------------------------------
__global__ void presplit(const float* __restrict__ X,
                         const float* __restrict__ W,
                         const float* __restrict__ Wo) {
    for (int idx = blockIdx.x * blockDim.x + threadIdx.x;
         idx < 1572864; idx += gridDim.x * blockDim.x) {
        const float* src; uint32_t* dst; int p;
        if (idx < 1048576)      { p = idx;           src = X;  dst = g_Xbf; }
        else if (idx < 1441792) { p = idx - 1048576; src = W;  dst = g_Wbf; }
        else                    { p = idx - 1441792; src = Wo; dst = g_Wobf; }
        int row = p >> 8, wc = p & 255;
        float2 f = *(const float2*)&src[(size_t)row * 512 + wc * 2];
        uint32_t hi, lo; split2(f, hi, lo);
        dst[(size_t)row * 512 + wc]       = hi;
        dst[(size_t)row * 512 + 256 + wc] = lo;
    }
}

// ---------------------------------------------------------------------------
// Unified bf16x3 GEMM, 2-stage cp.async pipeline. C = A @ B^T + bias, K=512.
// MODE 0: A=g_Xbf, B=g_Wbf -> scatter fp16 Q(hi/lo), K(single), V(hi/lo).
// MODE 1: A=g_Obf, B=g_Wobf -> fp32 out.
// ---------------------------------------------------------------------------
#define GSTR2 80
#define GSTAGE 40960
#define GEMM_SMEM 81920

template<int MODE>
__global__ __launch_bounds__(256, 2) void tc_gemm(const float* __restrict__ bias,
                                                  float* __restrict__ out) {
    extern __shared__ char smg[];
    const uint32_t sb = smem_u32(smg);
    const int tid = threadIdx.x;
    const int lane = tid & 31;
    const int w = tid >> 5;
    const int g = lane >> 2;
    const int tg = lane & 3;
    const int r8 = lane & 7;
    const int mlo = (lane >> 3) & 1;
    const int mhi = lane >> 4;
    const int bm = blockIdx.y * 128;
    const int bn = blockIdx.x * 128;

    const uint32_t* Aw = (MODE == 0) ? g_Xbf : g_Obf;
    const uint32_t* Bw = (MODE == 0) ? g_Wbf : g_Wobf;

    const int wm = (w >> 2) * 64;
    const int wn = (w & 3) * 32;

    float acc[4][4][4];
#pragma unroll
    for (int mb = 0; mb < 4; mb++)
#pragma unroll
        for (int nb = 0; nb < 4; nb++)
#pragma unroll
            for (int q = 0; q < 4; q++) acc[mb][nb][q] = 0.f;

    const uint32_t aA = sb + (uint32_t)((wm + mlo * 8 + r8) * GSTR2 + mhi * 16);
    const uint32_t aB = sb + 20480 + (uint32_t)((wn + mhi * 8 + r8) * GSTR2 + mlo * 16);

    auto stage_chunk = [&](int c, int s) {
        const int c0w = c * 16;
#pragma unroll
        for (int it = 0; it < 8; it++) {
            int item = tid + it * 256;
            int side = item >> 10;
            int idx = item & 1023;
            int row = idx >> 3;
            int q = idx & 7;
            int half = q >> 2;
            int c4 = q & 3;
            const uint32_t* src = (side ? Bw + (size_t)(bn + row) * 512
                                        : Aw + (size_t)(bm + row) * 512)
                                  + (half << 8) + c0w + c4 * 4;
            uint32_t dst = sb + s * GSTAGE + side * 20480 + half * 10240
                         + (uint32_t)(row * GSTR2 + c4 * 16);
            cpa16(dst, src);
        }
    };

    stage_chunk(0, 0);
    CP_COMMIT();

#pragma unroll 1
    for (int c = 0; c < 16; c++) {
        const int s = c & 1;
        if (c + 1 < 16) {
            stage_chunk(c + 1, s ^ 1);
            CP_COMMIT();
            CP_WAIT1();
        } else {
            CP_WAIT0();
        }
        __syncthreads();

        const uint32_t so = s * GSTAGE;
#pragma unroll
        for (int kk = 0; kk < 2; kk++) {
            uint32_t ah[4][4], al[4][4];
#pragma unroll
            for (int mb = 0; mb < 4; mb++) {
                ldsm4(ah[mb], aA + so + mb * (16 * GSTR2) + kk * 32);
                ldsm4(al[mb], aA + so + 10240 + mb * (16 * GSTR2) + kk * 32);
            }
#pragma unroll
            for (int j = 0; j < 2; j++) {
                uint32_t bh[4], bl[4];
                ldsm4(bh, aB + so + j * (16 * GSTR2) + kk * 32);
                ldsm4(bl, aB + so + 10240 + j * (16 * GSTR2) + kk * 32);
#pragma unroll
                for (int mb = 0; mb < 4; mb++) {
                    mma_bf16(acc[mb][2*j],   ah[mb], bh[0], bh[1]);
                    mma_bf16(acc[mb][2*j+1], ah[mb], bh[2], bh[3]);
                    mma_bf16(acc[mb][2*j],   ah[mb], bl[0], bl[1]);
                    mma_bf16(acc[mb][2*j+1], ah[mb], bl[2], bl[3]);
                    mma_bf16(acc[mb][2*j],   al[mb], bh[0], bh[1]);
                    mma_bf16(acc[mb][2*j+1], al[mb], bh[2], bh[3]);
                }
            }
        }
        __syncthreads();
    }

    // ---- epilogue ----
#pragma unroll
    for (int nb = 0; nb < 4; nb++) {
        if (MODE == 0) {
            const int nbb = bn + wn + nb * 8;
            const int h = nbb / 192;
            const int r = nbb - h * 192;
            const int t = r >> 6;
            const int wc = ((r & 63) >> 1) + tg;
            const float2 bia = *(const float2*)&bias[nbb + 2 * tg];
#pragma unroll
            for (int mb = 0; mb < 4; mb++) {
#pragma unroll
                for (int hf = 0; hf < 2; hf++) {
                    const int m = bm + wm + mb * 16 + g + hf * 8;
                    const int bi = m >> 11, ss = m & 2047;
                    const size_t b32 = ((size_t)(h * Bb + bi) * Ss + ss) * 32;
                    float2 v;
                    v.x = acc[mb][nb][2*hf]     + bia.x;
                    v.y = acc[mb][nb][2*hf + 1] + bia.y;
                    if (t == 0) {
                        uint32_t hi, lo; splith2(v, hi, lo);
                        g_Qh16[b32 + wc] = hi;
                        g_Ql16[b32 + wc] = lo;
                    } else if (t == 1) {
                        g_K16[b32 + wc] = pkh2(v.x, v.y);
                    } else {
                        uint32_t hi, lo; splith2(v, hi, lo);
                        g_Vh16[b32 + wc] = hi;
                        g_Vl16[b32 + wc] = lo;
                    }
                }
            }
        } else {
            const int n0 = bn + wn + nb * 8 + 2 * tg;
            const float2 bia = *(const float2*)&bias[n0];
#pragma unroll
            for (int mb = 0; mb < 4; mb++) {
                const int m0 = bm + wm + mb * 16 + g;
                float2 v0; v0.x = acc[mb][nb][0] + bia.x; v0.y = acc[mb][nb][1] + bia.y;
                float2 v1; v1.x = acc[mb][nb][2] + bia.x; v1.y = acc[mb][nb][3] + bia.y;
                *(float2*)&out[(size_t)m0 * 512 + n0] = v0;
                *(float2*)&out[(size_t)(m0 + 8) * 512 + n0] = v1;
            }
        }
    }
}

// ---------------------------------------------------------------------------
// Kernel 2: flash attention, fp16 reduced-pass mma, 2-stage cp.async pipeline.
// QK = Qhi*K + Qlo*K (Q split fp16 = exact; K single fp16).
// PV = P*Vhi + P*Vlo (V split = exact; P single fp16).
// smem: KV stage0 [0,27648) | stage1 [27648,55296) | Qhi [55296,73728) |
//       Qlo [73728,92160).  Per stage: K 9216 | Vhi 9216 | Vlo 9216 (row 144B)
// grid = (H, S/128, B): h fastest -> shift/mask L2 reuse across heads.
// ---------------------------------------------------------------------------
#define RSTR 144
#define KVSTAGE 27648
#define AOF_Q 55296
#define ATT_SMEM 92160

__global__ __launch_bounds__(256, 2) void attn_kernel(const float* __restrict__ shift,
                                                      const float* __restrict__ mask) {
    extern __shared__ char smc[];
    const uint32_t sb = smem_u32(smc);

    const int h  = blockIdx.x;
    const int qt = blockIdx.y;
    const int b  = blockIdx.z;
    const int tid = threadIdx.x;
    const int lane = tid & 31;
    const int w = tid >> 5;
    const int g = lane >> 2;
    const int tg = lane & 3;
    const int r8 = lane & 7;
    const int mlo = (lane >> 3) & 1;
    const int mhi = lane >> 4;

    const float c1  = 0.125f * 1.4426950408889634f;            // log2e / sqrt(64)
    const float hs2 = exp2f(-(float)h) * 1.4426950408889634f;  // head_scale * log2e

    const size_t hb = (size_t)(h * Bb + b) * Ss;
    const uint32_t* Qh = g_Qh16 + (hb + qt * 128) * 32;
    const uint32_t* Ql = g_Ql16 + (hb + qt * 128) * 32;
    const uint32_t* Kw = g_K16 + hb * 32;
    const uint32_t* Vh = g_Vh16 + hb * 32;
    const uint32_t* Vl = g_Vl16 + hb * 32;

    // ---- stage Q hi+lo once (2048 uint4 = 8 cp.async/thread) ----
#pragma unroll
    for (int it = 0; it < 8; it++) {
        int item = tid + it * 256;
        int half = item >> 10;
        int idx = item & 1023;
        int row = idx >> 3, c4 = idx & 7;
        cpa16(sb + AOF_Q + half * 18432 + (uint32_t)(row * RSTR + c4 * 16),
              (half ? Ql : Qh) + row * 32 + c4 * 4);
    }
    CP_COMMIT();

    // staging lambda: K/V tile kt (1536 uint4 = 6 cp.async/thread) into stage s
    auto stage_kv = [&](int kt, int s) {
#pragma unroll
        for (int it = 0; it < 6; it++) {
            int item = tid + it * 256;
            int sel = item >> 9;            // 0 = K, 1 = Vhi, 2 = Vlo
            int idx = item & 511;
            int row = idx >> 3, c4 = idx & 7;
            const uint32_t* src = (sel == 0 ? Kw : sel == 1 ? Vh : Vl)
                                  + kt * 2048 + row * 32 + c4 * 4;
            cpa16(sb + s * KVSTAGE + sel * 9216
                     + (uint32_t)(row * RSTR + c4 * 16), src);
        }
    };

    stage_kv(0, 0);
    CP_COMMIT();

    const uint32_t aQh = sb + AOF_Q + (uint32_t)((w * 16 + mlo * 8 + r8) * RSTR + mhi * 16);
    const uint32_t aKb = sb + (uint32_t)((mhi * 8 + r8) * RSTR + mlo * 16);
    const uint32_t aVb = sb + 9216 + (uint32_t)((mlo * 8 + r8) * RSTR + mhi * 16);

    float oacc[8][4];
#pragma unroll
    for (int nb = 0; nb < 8; nb++)
#pragma unroll
        for (int q = 0; q < 4; q++) oacc[nb][q] = 0.f;
    float ls0 = 0.f, ls1 = 0.f;

    const int q0 = qt * 128 + w * 16 + g;
    const float* shp = shift + ((size_t)b * Ss + q0) * Ss + 2 * tg;
    const float* mkp = mask  + ((size_t)b * Ss + q0) * Ss + 2 * tg;

#pragma unroll 1
    for (int kt = 0; kt < 32; kt++) {
        const int s = kt & 1;
        if (kt + 1 < 32) {
            stage_kv(kt + 1, s ^ 1);
            CP_COMMIT();
            CP_WAIT1();
        } else {
            CP_WAIT0();
        }
        __syncthreads();

        const uint32_t aK = aKb + s * KVSTAGE;
        const uint32_t aV = aVb + s * KVSTAGE;

        // ---- S = Q @ K^T : (Qhi + Qlo) x K, 2 passes ----
        float sacc[8][4];
#pragma unroll
        for (int nb = 0; nb < 8; nb++)
#pragma unroll
            for (int q = 0; q < 4; q++) sacc[nb][q] = 0.f;
#pragma unroll
        for (int kk = 0; kk < 4; kk++) {
            uint32_t qh[4], ql[4], kf[4];
            ldsm4(qh, aQh + kk * 32);
            ldsm4(ql, aQh + 18432 + kk * 32);
#pragma unroll
            for (int nbp = 0; nbp < 4; nbp++) {
                ldsm4(kf, aK + nbp * (16 * RSTR) + kk * 32);
                mma_f16(sacc[2*nbp],   qh, kf[0], kf[1]);
                mma_f16(sacc[2*nbp+1], qh, kf[2], kf[3]);
                mma_f16(sacc[2*nbp],   ql, kf[0], kf[1]);
                mma_f16(sacc[2*nbp+1], ql, kf[2], kf[3]);
            }
        }

        // ---- softmax in registers -> P fragments (single fp16) ----
        uint32_t pa[4][4];
        const float* sh_r = shp + kt * 64;
        const float* mk_r = mkp + kt * 64;
#pragma unroll
        for (int nb = 0; nb < 8; nb++) {
            float2 sh0 = *(const float2*)(sh_r + nb * 8);
            float2 mk0 = *(const float2*)(mk_r + nb * 8);
            float2 sh1 = *(const float2*)(sh_r + 8 * Ss + nb * 8);
            float2 mk1 = *(const float2*)(mk_r + 8 * Ss + nb * 8);
            float t00 = fmaf(sacc[nb][0], c1, -hs2 * sh0.x);
            float t01 = fmaf(sacc[nb][1], c1, -hs2 * sh0.y);
            float t10 = fmaf(sacc[nb][2], c1, -hs2 * sh1.x);
            float t11 = fmaf(sacc[nb][3], c1, -hs2 * sh1.y);
            float p00 = exp2f(t00) * mk0.x;
            float p01 = exp2f(t01) * mk0.y;
            float p10 = exp2f(t10) * mk1.x;
            float p11 = exp2f(t11) * mk1.y;
            ls0 += p00 + p01;
            ls1 += p10 + p11;
            uint32_t w0 = pkh2(p00, p01);
            uint32_t w1 = pkh2(p10, p11);
            const int kk2 = nb >> 1;
            if (nb & 1) { pa[kk2][2] = w0; pa[kk2][3] = w1; }
            else        { pa[kk2][0] = w0; pa[kk2][1] = w1; }
        }

        // ---- O += P @ (Vhi + Vlo), 2 passes, V via ldmatrix.trans ----
#pragma unroll
        for (int kk2 = 0; kk2 < 4; kk2++) {
#pragma unroll
            for (int nbp = 0; nbp < 4; nbp++) {
                uint32_t vf[4];
                ldsm4t(vf, aV + kk2 * (16 * RSTR) + nbp * 32);
                mma_f16(oacc[2*nbp],   pa[kk2], vf[0], vf[1]);
                mma_f16(oacc[2*nbp+1], pa[kk2], vf[2], vf[3]);
                ldsm4t(vf, aV + 9216 + kk2 * (16 * RSTR) + nbp * 32);
                mma_f16(oacc[2*nbp],   pa[kk2], vf[0], vf[1]);
                mma_f16(oacc[2*nbp+1], pa[kk2], vf[2], vf[3]);
            }
        }
        __syncthreads();   // all warps done with stage s before restage
    }

    // ---- epilogue: reduce row sums, scale, write pre-split O (bf16) ----
    ls0 += __shfl_xor_sync(0xffffffffu, ls0, 1);
    ls0 += __shfl_xor_sync(0xffffffffu, ls0, 2);
    ls1 += __shfl_xor_sync(0xffffffffu, ls1, 1);
    ls1 += __shfl_xor_sync(0xffffffffu, ls1, 2);
    const float i0 = 1.f / ls0;
    const float i1 = 1.f / ls1;

    const size_t base0 = ((size_t)b * Ss + q0) * 512 + h * 32 + tg;
#pragma unroll
    for (int nb = 0; nb < 8; nb++) {
        uint32_t hi, lo;
        split2(make_float2(oacc[nb][0] * i0, oacc[nb][1] * i0), hi, lo);
        g_Obf[base0 + nb * 4] = hi;
        g_Obf[base0 + 256 + nb * 4] = lo;
        split2(make_float2(oacc[nb][2] * i1, oacc[nb][3] * i1), hi, lo);
        g_Obf[base0 + 8 * 512 + nb * 4] = hi;
        g_Obf[base0 + 8 * 512 + 256 + nb * 4] = lo;
    }
}

// ---------------------------------------------------------------------------
extern "C" void kernel_launch(void* const* d_in, const int* in_sizes, int n_in,
                              void* d_out, int out_size) {
    const float* x     = (const float*)d_in[0];
    const float* shift = (const float*)d_in[1];
    const float* mask  = (const float*)d_in[2];
    const float* W     = (const float*)d_in[3];
    const float* b     = (const float*)d_in[4];
    const float* Wo    = (const float*)d_in[5];
    const float* bo    = (const float*)d_in[6];
    float* out = (float*)d_out;

    cudaFuncSetAttribute(tc_gemm<0>, cudaFuncAttributeMaxDynamicSharedMemorySize,
                         GEMM_SMEM);
    cudaFuncSetAttribute(tc_gemm<1>, cudaFuncAttributeMaxDynamicSharedMemorySize,
                         GEMM_SMEM);
    cudaFuncSetAttribute(attn_kernel, cudaFuncAttributeMaxDynamicSharedMemorySize,
                         ATT_SMEM);

    // split X/W/Wo once (bf16 hi/lo)
    presplit<<<2048, 256>>>(x, W, Wo);

    // QKV projection: bf16x3, pipelined; emits fp16 Q/K/V
    tc_gemm<0><<<dim3(12, 32), 256, GEMM_SMEM>>>(b, nullptr);

    // attention: fp16 reduced-pass, pipelined K/V
    attn_kernel<<<dim3(Hh, Ss / 128, Bb), 256, ATT_SMEM>>>(shift, mask);

    // output projection: bf16x3, pipelined
    tc_gemm<1><<<dim3(4, 32), 256, GEMM_SMEM>>>(bo, out);
}

// round 14
// speedup vs baseline: 1.3976x; 1.1849x over previous
#include <cuda_runtime.h>
#include <cuda_fp16.h>
#include <cstdint>

// Problem constants
#define Bb 2
#define Ss 2048
#define Dd 512
#define Hh 8
#define DHd 64
#define BSr (Bb*Ss)     // 4096 rows

// ---------------------------------------------------------------------------
// Global scratch.
//   bf16 hi/lo (u32 = bf16x2): g_Xbf/g_Wbf/g_Wobf/g_Obf [row][512]:
//        hi words [0:256), lo words [256:512)
//   fp16 single (u32 = f16x2): Q, K, V; [(h*Bb+b)*Ss+s][32] words
// ---------------------------------------------------------------------------
__device__ __align__(16) uint32_t g_Xbf [4096*512];
__device__ __align__(16) uint32_t g_Wbf [1536*512];
__device__ __align__(16) uint32_t g_Wobf[512*512];
__device__ __align__(16) uint32_t g_Obf [4096*512];
__device__ __align__(16) uint32_t g_Q16 [Hh*Bb*Ss*32];
__device__ __align__(16) uint32_t g_K16 [Hh*Bb*Ss*32];
__device__ __align__(16) uint32_t g_V16 [Hh*Bb*Ss*32];

// ---------------------------------------------------------------------------
// helpers
// ---------------------------------------------------------------------------
__device__ __forceinline__ void mma_bf16(float* d, const uint32_t* a,
                                         uint32_t b0, uint32_t b1) {
    asm volatile("mma.sync.aligned.m16n8k16.row.col.f32.bf16.bf16.f32 "
                 "{%0,%1,%2,%3}, {%4,%5,%6,%7}, {%8,%9}, {%0,%1,%2,%3};"
                 : "+f"(d[0]), "+f"(d[1]), "+f"(d[2]), "+f"(d[3])
                 : "r"(a[0]), "r"(a[1]), "r"(a[2]), "r"(a[3]), "r"(b0), "r"(b1));
}
__device__ __forceinline__ void mma_f16(float* d, const uint32_t* a,
                                        uint32_t b0, uint32_t b1) {
    asm volatile("mma.sync.aligned.m16n8k16.row.col.f32.f16.f16.f32 "
                 "{%0,%1,%2,%3}, {%4,%5,%6,%7}, {%8,%9}, {%0,%1,%2,%3};"
                 : "+f"(d[0]), "+f"(d[1]), "+f"(d[2]), "+f"(d[3])
                 : "r"(a[0]), "r"(a[1]), "r"(a[2]), "r"(a[3]), "r"(b0), "r"(b1));
}
__device__ __forceinline__ void ldsm4(uint32_t* r, uint32_t a) {
    asm volatile("ldmatrix.sync.aligned.m8n8.x4.shared.b16 {%0,%1,%2,%3}, [%4];"
                 : "=r"(r[0]), "=r"(r[1]), "=r"(r[2]), "=r"(r[3]) : "r"(a));
}
__device__ __forceinline__ void ldsm4t(uint32_t* r, uint32_t a) {
    asm volatile("ldmatrix.sync.aligned.m8n8.x4.trans.shared.b16 {%0,%1,%2,%3}, [%4];"
                 : "=r"(r[0]), "=r"(r[1]), "=r"(r[2]), "=r"(r[3]) : "r"(a));
}
__device__ __forceinline__ uint32_t smem_u32(const void* p) {
    uint32_t a;
    asm("{ .reg .u64 t; cvta.to.shared.u64 t, %1; cvt.u32.u64 %0, t; }"
        : "=r"(a) : "l"(p));
    return a;
}
// bf16 split helpers
__device__ __forceinline__ uint32_t bf2(float hi, float lo) {
    uint32_t r;
    asm("cvt.rn.bf16x2.f32 %0, %1, %2;" : "=r"(r) : "f"(hi), "f"(lo));
    return r;
}
__device__ __forceinline__ float bflo_f(uint32_t w) { return __uint_as_float(w << 16); }
__device__ __forceinline__ float bfhi_f(uint32_t w) { return __uint_as_float(w & 0xFFFF0000u); }
__device__ __forceinline__ void split2(float2 f, uint32_t& whi, uint32_t& wlo) {
    whi = bf2(f.y, f.x);
    float rx = f.x - bflo_f(whi);
    float ry = f.y - bfhi_f(whi);
    wlo = bf2(ry, rx);
}
// fp16: word = f16x2, x -> low half, y -> high half
__device__ __forceinline__ uint32_t pkh2(float x, float y) {
    __half2 h = __floats2half2_rn(x, y);
    return *(uint32_t*)&h;
}
__device__ __forceinline__ void cpa16(uint32_t dst, const uint32_t* src) {
    asm volatile("cp.async.cg.shared.global [%0], [%1], 16;"
                 :: "r"(dst), "l"(src) : "memory");
}
#define CP_COMMIT() asm volatile("cp.async.commit_group;" ::: "memory")
#define CP_WAIT0()  asm volatile("cp.async.wait_group 0;" ::: "memory")
#define CP_WAIT1()  asm volatile("cp.async.wait_group 1;" ::: "memory")

// ---------------------------------------------------------------------------
// Kernel 0: pre-split X, W, Wo into bf16 hi/lo buffers (runs once)
// ---------------------------------------------------------------------------
__global__ void presplit(const float* __restrict__ X,
                         const float* __restrict__ W,
                         const float* __restrict__ Wo) {
    for (int idx = blockIdx.x * blockDim.x + threadIdx.x;
         idx < 1572864; idx += gridDim.x * blockDim.x) {
        const float* src; uint32_t* dst; int p;
        if (idx < 1048576)      { p = idx;           src = X;  dst = g_Xbf; }
        else if (idx < 1441792) { p = idx - 1048576; src = W;  dst = g_Wbf; }
        else                    { p = idx - 1441792; src = Wo; dst = g_Wobf; }
        int row = p >> 8, wc = p & 255;
        float2 f = *(const float2*)&src[(size_t)row * 512 + wc * 2];
        uint32_t hi, lo; split2(f, hi, lo);
        dst[(size_t)row * 512 + wc]       = hi;
        dst[(size_t)row * 512 + 256 + wc] = lo;
    }
}

// ---------------------------------------------------------------------------
// Unified bf16x3 GEMM, 2-stage cp.async pipeline. C = A @ B^T + bias, K=512.
// MODE 0: A=g_Xbf, B=g_Wbf -> scatter single fp16 Q/K/V.
// MODE 1: A=g_Obf, B=g_Wobf -> fp32 out.
// ---------------------------------------------------------------------------
#define GSTR2 80
#define GSTAGE 40960
#define GEMM_SMEM 81920

template<int MODE>
__global__ __launch_bounds__(256, 2) void tc_gemm(const float* __restrict__ bias,
                                                  float* __restrict__ out) {
    extern __shared__ char smg[];
    const uint32_t sb = smem_u32(smg);
    const int tid = threadIdx.x;
    const int lane = tid & 31;
    const int w = tid >> 5;
    const int g = lane >> 2;
    const int tg = lane & 3;
    const int r8 = lane & 7;
    const int mlo = (lane >> 3) & 1;
    const int mhi = lane >> 4;
    const int bm = blockIdx.y * 128;
    const int bn = blockIdx.x * 128;

    const uint32_t* Aw = (MODE == 0) ? g_Xbf : g_Obf;
    const uint32_t* Bw = (MODE == 0) ? g_Wbf : g_Wobf;

    const int wm = (w >> 2) * 64;
    const int wn = (w & 3) * 32;

    float acc[4][4][4];
#pragma unroll
    for (int mb = 0; mb < 4; mb++)
#pragma unroll
        for (int nb = 0; nb < 4; nb++)
#pragma unroll
            for (int q = 0; q < 4; q++) acc[mb][nb][q] = 0.f;

    const uint32_t aA = sb + (uint32_t)((wm + mlo * 8 + r8) * GSTR2 + mhi * 16);
    const uint32_t aB = sb + 20480 + (uint32_t)((wn + mhi * 8 + r8) * GSTR2 + mlo * 16);

    auto stage_chunk = [&](int c, int s) {
        const int c0w = c * 16;
#pragma unroll
        for (int it = 0; it < 8; it++) {
            int item = tid + it * 256;
            int side = item >> 10;
            int idx = item & 1023;
            int row = idx >> 3;
            int q = idx & 7;
            int half = q >> 2;
            int c4 = q & 3;
            const uint32_t* src = (side ? Bw + (size_t)(bn + row) * 512
                                        : Aw + (size_t)(bm + row) * 512)
                                  + (half << 8) + c0w + c4 * 4;
            uint32_t dst = sb + s * GSTAGE + side * 20480 + half * 10240
                         + (uint32_t)(row * GSTR2 + c4 * 16);
            cpa16(dst, src);
        }
    };

    stage_chunk(0, 0);
    CP_COMMIT();

#pragma unroll 1
    for (int c = 0; c < 16; c++) {
        const int s = c & 1;
        if (c + 1 < 16) {
            stage_chunk(c + 1, s ^ 1);
            CP_COMMIT();
            CP_WAIT1();
        } else {
            CP_WAIT0();
        }
        __syncthreads();

        const uint32_t so = s * GSTAGE;
#pragma unroll
        for (int kk = 0; kk < 2; kk++) {
            uint32_t ah[4][4], al[4][4];
#pragma unroll
            for (int mb = 0; mb < 4; mb++) {
                ldsm4(ah[mb], aA + so + mb * (16 * GSTR2) + kk * 32);
                ldsm4(al[mb], aA + so + 10240 + mb * (16 * GSTR2) + kk * 32);
            }
#pragma unroll
            for (int j = 0; j < 2; j++) {
                uint32_t bh[4], bl[4];
                ldsm4(bh, aB + so + j * (16 * GSTR2) + kk * 32);
                ldsm4(bl, aB + so + 10240 + j * (16 * GSTR2) + kk * 32);
#pragma unroll
                for (int mb = 0; mb < 4; mb++) {
                    mma_bf16(acc[mb][2*j],   ah[mb], bh[0], bh[1]);
                    mma_bf16(acc[mb][2*j+1], ah[mb], bh[2], bh[3]);
                    mma_bf16(acc[mb][2*j],   ah[mb], bl[0], bl[1]);
                    mma_bf16(acc[mb][2*j+1], ah[mb], bl[2], bl[3]);
                    mma_bf16(acc[mb][2*j],   al[mb], bh[0], bh[1]);
                    mma_bf16(acc[mb][2*j+1], al[mb], bh[2], bh[3]);
                }
            }
        }
        __syncthreads();
    }

    // ---- epilogue ----
#pragma unroll
    for (int nb = 0; nb < 4; nb++) {
        if (MODE == 0) {
            const int nbb = bn + wn + nb * 8;
            const int h = nbb / 192;
            const int r = nbb - h * 192;
            const int t = r >> 6;
            uint32_t* dst = (t == 0) ? g_Q16 : (t == 1) ? g_K16 : g_V16;
            const int wc = ((r & 63) >> 1) + tg;
            const float2 bia = *(const float2*)&bias[nbb + 2 * tg];
#pragma unroll
            for (int mb = 0; mb < 4; mb++) {
#pragma unroll
                for (int hf = 0; hf < 2; hf++) {
                    const int m = bm + wm + mb * 16 + g + hf * 8;
                    const int bi = m >> 11, ss = m & 2047;
                    dst[((size_t)(h * Bb + bi) * Ss + ss) * 32 + wc] =
                        pkh2(acc[mb][nb][2*hf] + bia.x,
                             acc[mb][nb][2*hf + 1] + bia.y);
                }
            }
        } else {
            const int n0 = bn + wn + nb * 8 + 2 * tg;
            const float2 bia = *(const float2*)&bias[n0];
#pragma unroll
            for (int mb = 0; mb < 4; mb++) {
                const int m0 = bm + wm + mb * 16 + g;
                float2 v0; v0.x = acc[mb][nb][0] + bia.x; v0.y = acc[mb][nb][1] + bia.y;
                float2 v1; v1.x = acc[mb][nb][2] + bia.x; v1.y = acc[mb][nb][3] + bia.y;
                *(float2*)&out[(size_t)m0 * 512 + n0] = v0;
                *(float2*)&out[(size_t)(m0 + 8) * 512 + n0] = v1;
            }
        }
    }
}

// ---------------------------------------------------------------------------
// Kernel 2: flash attention, single-pass fp16 mma, 2-stage cp.async pipeline.
// Q,K,V all single fp16 (calibrated error: 4 quant sources ~= 3.4e-4 total).
// smem: KV stage0 [0,18432): K [0,9216) V [9216,18432);
//       KV stage1 [18432,36864); Q [36864,55296). Row stride 144B.
// grid = (H, S/128, B): h fastest -> shift/mask L2 reuse across heads.
// ---------------------------------------------------------------------------
#define RSTR 144
#define KVSTAGE 18432
#define AOF_Q 36864
#define ATT_SMEM 55296

__global__ __launch_bounds__(256, 2) void attn_kernel(const float* __restrict__ shift,
                                                      const float* __restrict__ mask) {
    extern __shared__ char smc[];
    const uint32_t sb = smem_u32(smc);

    const int h  = blockIdx.x;
    const int qt = blockIdx.y;
    const int b  = blockIdx.z;
    const int tid = threadIdx.x;
    const int lane = tid & 31;
    const int w = tid >> 5;
    const int g = lane >> 2;
    const int tg = lane & 3;
    const int r8 = lane & 7;
    const int mlo = (lane >> 3) & 1;
    const int mhi = lane >> 4;

    const float c1  = 0.125f * 1.4426950408889634f;            // log2e / sqrt(64)
    const float hs2 = exp2f(-(float)h) * 1.4426950408889634f;  // head_scale * log2e

    const size_t hb = (size_t)(h * Bb + b) * Ss;
    const uint32_t* Qw = g_Q16 + (hb + qt * 128) * 32;
    const uint32_t* Kw = g_K16 + hb * 32;
    const uint32_t* Vw = g_V16 + hb * 32;

    // ---- stage Q once (1024 uint4 = 4 cp.async/thread) ----
#pragma unroll
    for (int it = 0; it < 4; it++) {
        int item = tid + it * 256;
        int row = item >> 3, c4 = item & 7;
        cpa16(sb + AOF_Q + (uint32_t)(row * RSTR + c4 * 16),
              Qw + row * 32 + c4 * 4);
    }
    CP_COMMIT();

    // staging lambda: K/V tile kt (1024 uint4 = 4 cp.async/thread) into stage s
    auto stage_kv = [&](int kt, int s) {
#pragma unroll
        for (int it = 0; it < 4; it++) {
            int item = tid + it * 256;
            int side = item >> 9;           // 0 = K, 1 = V
            int idx = item & 511;
            int row = idx >> 3, c4 = idx & 7;
            const uint32_t* src = (side ? Vw : Kw) + kt * 2048 + row * 32 + c4 * 4;
            cpa16(sb + s * KVSTAGE + side * 9216
                     + (uint32_t)(row * RSTR + c4 * 16), src);
        }
    };

    stage_kv(0, 0);
    CP_COMMIT();

    const uint32_t aQ = sb + AOF_Q + (uint32_t)((w * 16 + mlo * 8 + r8) * RSTR + mhi * 16);
    const uint32_t aKb = sb + (uint32_t)((mhi * 8 + r8) * RSTR + mlo * 16);
    const uint32_t aVb = sb + 9216 + (uint32_t)((mlo * 8 + r8) * RSTR + mhi * 16);

    float oacc[8][4];
#pragma unroll
    for (int nb = 0; nb < 8; nb++)
#pragma unroll
        for (int q = 0; q < 4; q++) oacc[nb][q] = 0.f;
    float ls0 = 0.f, ls1 = 0.f;

    const int q0 = qt * 128 + w * 16 + g;
    const float* shp = shift + ((size_t)b * Ss + q0) * Ss + 2 * tg;
    const float* mkp = mask  + ((size_t)b * Ss + q0) * Ss + 2 * tg;

#pragma unroll 1
    for (int kt = 0; kt < 32; kt++) {
        const int s = kt & 1;
        if (kt + 1 < 32) {
            stage_kv(kt + 1, s ^ 1);
            CP_COMMIT();
            CP_WAIT1();
        } else {
            CP_WAIT0();
        }
        __syncthreads();

        const uint32_t aK = aKb + s * KVSTAGE;
        const uint32_t aV = aVb + s * KVSTAGE;

        // ---- S = Q @ K^T (single fp16 pass) ----
        float sacc[8][4];
#pragma unroll
        for (int nb = 0; nb < 8; nb++)
#pragma unroll
            for (int q = 0; q < 4; q++) sacc[nb][q] = 0.f;
#pragma unroll
        for (int kk = 0; kk < 4; kk++) {
            uint32_t qf[4], kf[4];
            ldsm4(qf, aQ + kk * 32);
#pragma unroll
            for (int nbp = 0; nbp < 4; nbp++) {
                ldsm4(kf, aK + nbp * (16 * RSTR) + kk * 32);
                mma_f16(sacc[2*nbp],   qf, kf[0], kf[1]);
                mma_f16(sacc[2*nbp+1], qf, kf[2], kf[3]);
            }
        }

        // ---- softmax in registers -> P fragments (single fp16) ----
        uint32_t pa[4][4];
        const float* sh_r = shp + kt * 64;
        const float* mk_r = mkp + kt * 64;
#pragma unroll
        for (int nb = 0; nb < 8; nb++) {
            float2 sh0 = *(const float2*)(sh_r + nb * 8);
            float2 mk0 = *(const float2*)(mk_r + nb * 8);
            float2 sh1 = *(const float2*)(sh_r + 8 * Ss + nb * 8);
            float2 mk1 = *(const float2*)(mk_r + 8 * Ss + nb * 8);
            float t00 = fmaf(sacc[nb][0], c1, -hs2 * sh0.x);
            float t01 = fmaf(sacc[nb][1], c1, -hs2 * sh0.y);
            float t10 = fmaf(sacc[nb][2], c1, -hs2 * sh1.x);
            float t11 = fmaf(sacc[nb][3], c1, -hs2 * sh1.y);
            float p00 = exp2f(t00) * mk0.x;
            float p01 = exp2f(t01) * mk0.y;
            float p10 = exp2f(t10) * mk1.x;
            float p11 = exp2f(t11) * mk1.y;
            ls0 += p00 + p01;
            ls1 += p10 + p11;
            uint32_t w0 = pkh2(p00, p01);
            uint32_t w1 = pkh2(p10, p11);
            const int kk2 = nb >> 1;
            if (nb & 1) { pa[kk2][2] = w0; pa[kk2][3] = w1; }
            else        { pa[kk2][0] = w0; pa[kk2][1] = w1; }
        }

        // ---- O += P @ V (single fp16 pass, V via ldmatrix.trans) ----
#pragma unroll
        for (int kk2 = 0; kk2 < 4; kk2++) {
#pragma unroll
            for (int nbp = 0; nbp < 4; nbp++) {
                uint32_t vf[4];
                ldsm4t(vf, aV + kk2 * (16 * RSTR) + nbp * 32);
                mma_f16(oacc[2*nbp],   pa[kk2], vf[0], vf[1]);
                mma_f16(oacc[2*nbp+1], pa[kk2], vf[2], vf[3]);
            }
        }
        __syncthreads();   // all warps done with stage s before restage
    }

    // ---- epilogue: reduce row sums, scale, write pre-split O (bf16) ----
    ls0 += __shfl_xor_sync(0xffffffffu, ls0, 1);
    ls0 += __shfl_xor_sync(0xffffffffu, ls0, 2);
    ls1 += __shfl_xor_sync(0xffffffffu, ls1, 1);
    ls1 += __shfl_xor_sync(0xffffffffu, ls1, 2);
    const float i0 = 1.f / ls0;
    const float i1 = 1.f / ls1;

    const size_t base0 = ((size_t)b * Ss + q0) * 512 + h * 32 + tg;
#pragma unroll
    for (int nb = 0; nb < 8; nb++) {
        uint32_t hi, lo;
        split2(make_float2(oacc[nb][0] * i0, oacc[nb][1] * i0), hi, lo);
        g_Obf[base0 + nb * 4] = hi;
        g_Obf[base0 + 256 + nb * 4] = lo;
        split2(make_float2(oacc[nb][2] * i1, oacc[nb][3] * i1), hi, lo);
        g_Obf[base0 + 8 * 512 + nb * 4] = hi;
        g_Obf[base0 + 8 * 512 + 256 + nb * 4] = lo;
    }
}

// ---------------------------------------------------------------------------
extern "C" void kernel_launch(void* const* d_in, const int* in_sizes, int n_in,
                              void* d_out, int out_size) {
    const float* x     = (const float*)d_in[0];
    const float* shift = (const float*)d_in[1];
    const float* mask  = (const float*)d_in[2];
    const float* W     = (const float*)d_in[3];
    const float* b     = (const float*)d_in[4];
    const float* Wo    = (const float*)d_in[5];
    const float* bo    = (const float*)d_in[6];
    float* out = (float*)d_out;

    cudaFuncSetAttribute(tc_gemm<0>, cudaFuncAttributeMaxDynamicSharedMemorySize,
                         GEMM_SMEM);
    cudaFuncSetAttribute(tc_gemm<1>, cudaFuncAttributeMaxDynamicSharedMemorySize,
                         GEMM_SMEM);
    cudaFuncSetAttribute(attn_kernel, cudaFuncAttributeMaxDynamicSharedMemorySize,
                         ATT_SMEM);

    // split X/W/Wo once (bf16 hi/lo)
    presplit<<<2048, 256>>>(x, W, Wo);

    // QKV projection: bf16x3, pipelined; emits single fp16 Q/K/V
    tc_gemm<0><<<dim3(12, 32), 256, GEMM_SMEM>>>(b, nullptr);

    // attention: single-pass fp16, pipelined K/V
    attn_kernel<<<dim3(Hh, Ss / 128, Bb), 256, ATT_SMEM>>>(shift, mask);

    // output projection: bf16x3, pipelined
    tc_gemm<1><<<dim3(4, 32), 256, GEMM_SMEM>>>(bo, out);
}

// round 15
// speedup vs baseline: 1.7425x; 1.2468x over previous
#include <cuda_runtime.h>
#include <cuda_fp16.h>
#include <cstdint>

// Problem constants
#define Bb 2
#define Ss 2048
#define Dd 512
#define Hh 8
#define DHd 64
#define BSr (Bb*Ss)     // 4096 rows

// ---------------------------------------------------------------------------
// Global scratch (all u32 = f16x2 word = 2 fp16 elements).
//   g_Xh16/g_Xl16 [4096][256] : X split hi/lo fp16
//   g_W16 [1536][256], g_Wo16 [512][256] : weights single fp16
//   g_Oh16/g_Ol16 [4096][256] : attention output split hi/lo fp16
//   g_Q16/g_K16/g_V16 [(h*Bb+b)*Ss+s][32] : single fp16
//   g_SM16 [b][q][1024] : fused shift/mask fp16 (masked -> 65504)
// ---------------------------------------------------------------------------
__device__ __align__(16) uint32_t g_Xh16[4096*256];
__device__ __align__(16) uint32_t g_Xl16[4096*256];
__device__ __align__(16) uint32_t g_W16 [1536*256];
__device__ __align__(16) uint32_t g_Wo16[512*256];
__device__ __align__(16) uint32_t g_Oh16[4096*256];
__device__ __align__(16) uint32_t g_Ol16[4096*256];
__device__ __align__(16) uint32_t g_Q16 [Hh*Bb*Ss*32];
__device__ __align__(16) uint32_t g_K16 [Hh*Bb*Ss*32];
__device__ __align__(16) uint32_t g_V16 [Hh*Bb*Ss*32];
__device__ __align__(16) uint32_t g_SM16[(size_t)Bb*Ss*1024];

// ---------------------------------------------------------------------------
// helpers
// ---------------------------------------------------------------------------
__device__ __forceinline__ void mma_f16(float* d, const uint32_t* a,
                                        uint32_t b0, uint32_t b1) {
    asm volatile("mma.sync.aligned.m16n8k16.row.col.f32.f16.f16.f32 "
                 "{%0,%1,%2,%3}, {%4,%5,%6,%7}, {%8,%9}, {%0,%1,%2,%3};"
                 : "+f"(d[0]), "+f"(d[1]), "+f"(d[2]), "+f"(d[3])
                 : "r"(a[0]), "r"(a[1]), "r"(a[2]), "r"(a[3]), "r"(b0), "r"(b1));
}
__device__ __forceinline__ void ldsm4(uint32_t* r, uint32_t a) {
    asm volatile("ldmatrix.sync.aligned.m8n8.x4.shared.b16 {%0,%1,%2,%3}, [%4];"
                 : "=r"(r[0]), "=r"(r[1]), "=r"(r[2]), "=r"(r[3]) : "r"(a));
}
__device__ __forceinline__ void ldsm4t(uint32_t* r, uint32_t a) {
    asm volatile("ldmatrix.sync.aligned.m8n8.x4.trans.shared.b16 {%0,%1,%2,%3}, [%4];"
                 : "=r"(r[0]), "=r"(r[1]), "=r"(r[2]), "=r"(r[3]) : "r"(a));
}
__device__ __forceinline__ uint32_t smem_u32(const void* p) {
    uint32_t a;
    asm("{ .reg .u64 t; cvta.to.shared.u64 t, %1; cvt.u32.u64 %0, t; }"
        : "=r"(a) : "l"(p));
    return a;
}
// fp16: word = f16x2, x -> low half, y -> high half
__device__ __forceinline__ uint32_t pkh2(float x, float y) {
    __half2 h = __floats2half2_rn(x, y);
    return *(uint32_t*)&h;
}
__device__ __forceinline__ void splith2(float2 f, uint32_t& whi, uint32_t& wlo) {
    __half2 h = __floats2half2_rn(f.x, f.y);
    whi = *(uint32_t*)&h;
    float2 bk = __half22float2(h);
    __half2 l = __floats2half2_rn(f.x - bk.x, f.y - bk.y);
    wlo = *(uint32_t*)&l;
}
__device__ __forceinline__ float2 uph2(uint32_t w) {
    return __half22float2(*(__half2*)&w);
}
__device__ __forceinline__ void cpa16(uint32_t dst, const uint32_t* src) {
    asm volatile("cp.async.cg.shared.global [%0], [%1], 16;"
                 :: "r"(dst), "l"(src) : "memory");
}
#define CP_COMMIT() asm volatile("cp.async.commit_group;" ::: "memory")
#define CP_WAIT0()  asm volatile("cp.async.wait_group 0;" ::: "memory")
#define CP_WAIT1()  asm volatile("cp.async.wait_group 1;" ::: "memory")

// ---------------------------------------------------------------------------
// Kernel 0: precompute fp16 tables.
//   X -> Xhi/Xlo (split, exact to ~2^-22), W/Wo -> single fp16,
//   shm = mask ? shift : 65504  (masked logits -> exp2 underflows to 0.0)
// ---------------------------------------------------------------------------
#define PRE_TOTAL (1048576 + 393216 + 131072 + 4194304)

__global__ void presplit(const float* __restrict__ X,
                         const float* __restrict__ W,
                         const float* __restrict__ Wo,
                         const float* __restrict__ shift,
                         const float* __restrict__ mask) {
    for (int idx = blockIdx.x * blockDim.x + threadIdx.x;
         idx < PRE_TOTAL; idx += gridDim.x * blockDim.x) {
        if (idx < 1048576) {                    // X split
            int row = idx >> 8, wc = idx & 255;
            float2 f = *(const float2*)&X[(size_t)row * 512 + wc * 2];
            uint32_t hi, lo; splith2(f, hi, lo);
            g_Xh16[(size_t)row * 256 + wc] = hi;
            g_Xl16[(size_t)row * 256 + wc] = lo;
        } else if (idx < 1441792) {             // W single
            int p = idx - 1048576;
            int row = p >> 8, wc = p & 255;
            float2 f = *(const float2*)&W[(size_t)row * 512 + wc * 2];
            g_W16[(size_t)row * 256 + wc] = pkh2(f.x, f.y);
        } else if (idx < 1572864) {             // Wo single
            int p = idx - 1441792;
            int row = p >> 8, wc = p & 255;
            float2 f = *(const float2*)&Wo[(size_t)row * 512 + wc * 2];
            g_Wo16[(size_t)row * 256 + wc] = pkh2(f.x, f.y);
        } else {                                // fused shift/mask
            int p = idx - 1572864;
            int row = p >> 10, wc = p & 1023;   // row in [0,4096), col pair
            float2 sh = *(const float2*)&shift[(size_t)row * 2048 + wc * 2];
            float2 mk = *(const float2*)&mask[(size_t)row * 2048 + wc * 2];
            float v0 = (mk.x != 0.f) ? sh.x : 65504.f;
            float v1 = (mk.y != 0.f) ? sh.y : 65504.f;
            g_SM16[(size_t)row * 1024 + wc] = pkh2(v0, v1);
        }
    }
}

// ---------------------------------------------------------------------------
// Unified fp16 2-pass GEMM: C = (Ahi+Alo) @ B^T + bias, K=512.
// A split fp16 (exact), B single fp16 (calibrated quant ~1.7e-4).
// CTA 128x128, 8 warps 2(M)x4(N), K chunks of 32 elems, 2-stage cp.async.
// MODE 0: A=Xhi/Xlo, B=W16 -> scatter single fp16 Q/K/V.
// MODE 1: A=Ohi/Olo, B=Wo16 -> fp32 out.
// ---------------------------------------------------------------------------
#define GSTR2 80
#define GSTAGE 30720          // Ahi 10240 | Alo 10240 | B 10240
#define GEMM_SMEM 61440

template<int MODE>
__global__ __launch_bounds__(256, 2) void tc_gemm(const float* __restrict__ bias,
                                                  float* __restrict__ out) {
    extern __shared__ char smg[];
    const uint32_t sb = smem_u32(smg);
    const int tid = threadIdx.x;
    const int lane = tid & 31;
    const int w = tid >> 5;
    const int g = lane >> 2;
    const int tg = lane & 3;
    const int r8 = lane & 7;
    const int mlo = (lane >> 3) & 1;
    const int mhi = lane >> 4;
    const int bm = blockIdx.y * 128;
    const int bn = blockIdx.x * 128;

    const uint32_t* Ah = (MODE == 0) ? g_Xh16 : g_Oh16;
    const uint32_t* Al = (MODE == 0) ? g_Xl16 : g_Ol16;
    const uint32_t* Bw = (MODE == 0) ? g_W16 : g_Wo16;

    const int wm = (w >> 2) * 64;
    const int wn = (w & 3) * 32;

    float acc[4][4][4];
#pragma unroll
    for (int mb = 0; mb < 4; mb++)
#pragma unroll
        for (int nb = 0; nb < 4; nb++)
#pragma unroll
            for (int q = 0; q < 4; q++) acc[mb][nb][q] = 0.f;

    const uint32_t aA = sb + (uint32_t)((wm + mlo * 8 + r8) * GSTR2 + mhi * 16);
    const uint32_t aB = sb + 20480 + (uint32_t)((wn + mhi * 8 + r8) * GSTR2 + mlo * 16);

    // stage chunk c (16 words/row for Ahi, Alo, B) into stage s
    auto stage_chunk = [&](int c, int s) {
        const int c0w = c * 16;
#pragma unroll
        for (int it = 0; it < 6; it++) {
            int item = tid + it * 256;
            int sel = item >> 9;            // 0=Ahi, 1=Alo, 2=B
            int idx = item & 511;
            int row = idx >> 2;             // 0..127
            int c4 = idx & 3;
            const uint32_t* src =
                (sel == 0 ? Ah + (size_t)(bm + row) * 256
               : sel == 1 ? Al + (size_t)(bm + row) * 256
                          : Bw + (size_t)(bn + row) * 256)
                + c0w + c4 * 4;
            uint32_t dst = sb + s * GSTAGE + sel * 10240
                         + (uint32_t)(row * GSTR2 + c4 * 16);
            cpa16(dst, src);
        }
    };

    stage_chunk(0, 0);
    CP_COMMIT();

#pragma unroll 1
    for (int c = 0; c < 16; c++) {
        const int s = c & 1;
        if (c + 1 < 16) {
            stage_chunk(c + 1, s ^ 1);
            CP_COMMIT();
            CP_WAIT1();
        } else {
            CP_WAIT0();
        }
        __syncthreads();

        const uint32_t so = s * GSTAGE;
#pragma unroll
        for (int kk = 0; kk < 2; kk++) {
            uint32_t ah[4][4], al[4][4];
#pragma unroll
            for (int mb = 0; mb < 4; mb++) {
                ldsm4(ah[mb], aA + so + mb * (16 * GSTR2) + kk * 32);
                ldsm4(al[mb], aA + so + 10240 + mb * (16 * GSTR2) + kk * 32);
            }
#pragma unroll
            for (int j = 0; j < 2; j++) {
                uint32_t bf[4];
                ldsm4(bf, aB + so + j * (16 * GSTR2) + kk * 32);
#pragma unroll
                for (int mb = 0; mb < 4; mb++) {
                    mma_f16(acc[mb][2*j],   ah[mb], bf[0], bf[1]);
                    mma_f16(acc[mb][2*j+1], ah[mb], bf[2], bf[3]);
                    mma_f16(acc[mb][2*j],   al[mb], bf[0], bf[1]);
                    mma_f16(acc[mb][2*j+1], al[mb], bf[2], bf[3]);
                }
            }
        }
        __syncthreads();
    }

    // ---- epilogue ----
#pragma unroll
    for (int nb = 0; nb < 4; nb++) {
        if (MODE == 0) {
            const int nbb = bn + wn + nb * 8;
            const int h = nbb / 192;
            const int r = nbb - h * 192;
            const int t = r >> 6;
            uint32_t* dst = (t == 0) ? g_Q16 : (t == 1) ? g_K16 : g_V16;
            const int wc = ((r & 63) >> 1) + tg;
            const float2 bia = *(const float2*)&bias[nbb + 2 * tg];
#pragma unroll
            for (int mb = 0; mb < 4; mb++) {
#pragma unroll
                for (int hf = 0; hf < 2; hf++) {
                    const int m = bm + wm + mb * 16 + g + hf * 8;
                    const int bi = m >> 11, ss = m & 2047;
                    dst[((size_t)(h * Bb + bi) * Ss + ss) * 32 + wc] =
                        pkh2(acc[mb][nb][2*hf] + bia.x,
                             acc[mb][nb][2*hf + 1] + bia.y);
                }
            }
        } else {
            const int n0 = bn + wn + nb * 8 + 2 * tg;
            const float2 bia = *(const float2*)&bias[n0];
#pragma unroll
            for (int mb = 0; mb < 4; mb++) {
                const int m0 = bm + wm + mb * 16 + g;
                float2 v0; v0.x = acc[mb][nb][0] + bia.x; v0.y = acc[mb][nb][1] + bia.y;
                float2 v1; v1.x = acc[mb][nb][2] + bia.x; v1.y = acc[mb][nb][3] + bia.y;
                *(float2*)&out[(size_t)m0 * 512 + n0] = v0;
                *(float2*)&out[(size_t)(m0 + 8) * 512 + n0] = v1;
            }
        }
    }
}

// ---------------------------------------------------------------------------
// Kernel 2: flash attention, single-pass fp16 mma, 2-stage cp.async pipeline,
// fused fp16 shift/mask table (masked -> 65504 -> exp2 underflow -> exact 0).
// smem: KV stage0 [0,18432): K [0,9216) V [9216,18432);
//       KV stage1 [18432,36864); Q [36864,55296). Row stride 144B.
// O written split fp16 hi/lo for the out-projection.
// grid = (H, S/128, B): h fastest -> shm L2 reuse across heads.
// ---------------------------------------------------------------------------
#define RSTR 144
#define KVSTAGE 18432
#define AOF_Q 36864
#define ATT_SMEM 55296

__global__ __launch_bounds__(256, 2) void attn_kernel() {
    extern __shared__ char smc[];
    const uint32_t sb = smem_u32(smc);

    const int h  = blockIdx.x;
    const int qt = blockIdx.y;
    const int b  = blockIdx.z;
    const int tid = threadIdx.x;
    const int lane = tid & 31;
    const int w = tid >> 5;
    const int g = lane >> 2;
    const int tg = lane & 3;
    const int r8 = lane & 7;
    const int mlo = (lane >> 3) & 1;
    const int mhi = lane >> 4;

    const float c1  = 0.125f * 1.4426950408889634f;            // log2e / sqrt(64)
    const float hs2 = exp2f(-(float)h) * 1.4426950408889634f;  // head_scale * log2e

    const size_t hb = (size_t)(h * Bb + b) * Ss;
    const uint32_t* Qw = g_Q16 + (hb + qt * 128) * 32;
    const uint32_t* Kw = g_K16 + hb * 32;
    const uint32_t* Vw = g_V16 + hb * 32;

    // ---- stage Q once (1024 uint4 = 4 cp.async/thread) ----
#pragma unroll
    for (int it = 0; it < 4; it++) {
        int item = tid + it * 256;
        int row = item >> 3, c4 = item & 7;
        cpa16(sb + AOF_Q + (uint32_t)(row * RSTR + c4 * 16),
              Qw + row * 32 + c4 * 4);
    }
    CP_COMMIT();

    // staging lambda: K/V tile kt (1024 uint4 = 4 cp.async/thread) into stage s
    auto stage_kv = [&](int kt, int s) {
#pragma unroll
        for (int it = 0; it < 4; it++) {
            int item = tid + it * 256;
            int side = item >> 9;           // 0 = K, 1 = V
            int idx = item & 511;
            int row = idx >> 3, c4 = idx & 7;
            const uint32_t* src = (side ? Vw : Kw) + kt * 2048 + row * 32 + c4 * 4;
            cpa16(sb + s * KVSTAGE + side * 9216
                     + (uint32_t)(row * RSTR + c4 * 16), src);
        }
    };

    stage_kv(0, 0);
    CP_COMMIT();

    const uint32_t aQ = sb + AOF_Q + (uint32_t)((w * 16 + mlo * 8 + r8) * RSTR + mhi * 16);
    const uint32_t aKb = sb + (uint32_t)((mhi * 8 + r8) * RSTR + mlo * 16);
    const uint32_t aVb = sb + 9216 + (uint32_t)((mlo * 8 + r8) * RSTR + mhi * 16);

    float oacc[8][4];
#pragma unroll
    for (int nb = 0; nb < 8; nb++)
#pragma unroll
        for (int q = 0; q < 4; q++) oacc[nb][q] = 0.f;
    float ls0 = 0.f, ls1 = 0.f;

    const int q0 = qt * 128 + w * 16 + g;
    // fused shift/mask words: row length 1024 words; this thread covers
    // word col kt*32 + nb*4 + tg for rows q0 and q0+8
    const uint32_t* shmp = g_SM16 + ((size_t)b * Ss + q0) * 1024 + tg;

#pragma unroll 1
    for (int kt = 0; kt < 32; kt++) {
        const int s = kt & 1;
        if (kt + 1 < 32) {
            stage_kv(kt + 1, s ^ 1);
            CP_COMMIT();
            CP_WAIT1();
        } else {
            CP_WAIT0();
        }
        __syncthreads();

        const uint32_t aK = aKb + s * KVSTAGE;
        const uint32_t aV = aVb + s * KVSTAGE;

        // ---- S = Q @ K^T (single fp16 pass) ----
        float sacc[8][4];
#pragma unroll
        for (int nb = 0; nb < 8; nb++)
#pragma unroll
            for (int q = 0; q < 4; q++) sacc[nb][q] = 0.f;
#pragma unroll
        for (int kk = 0; kk < 4; kk++) {
            uint32_t qf[4], kf[4];
            ldsm4(qf, aQ + kk * 32);
#pragma unroll
            for (int nbp = 0; nbp < 4; nbp++) {
                ldsm4(kf, aK + nbp * (16 * RSTR) + kk * 32);
                mma_f16(sacc[2*nbp],   qf, kf[0], kf[1]);
                mma_f16(sacc[2*nbp+1], qf, kf[2], kf[3]);
            }
        }

        // ---- softmax -> P fragments (single fp16) ----
        uint32_t pa[4][4];
        const uint32_t* sm_r = shmp + kt * 32;
#pragma unroll
        for (int nb = 0; nb < 8; nb++) {
            float2 s0 = uph2(sm_r[nb * 4]);
            float2 s1 = uph2(sm_r[8 * 1024 + nb * 4]);
            float p00 = exp2f(fmaf(sacc[nb][0], c1, -hs2 * s0.x));
            float p01 = exp2f(fmaf(sacc[nb][1], c1, -hs2 * s0.y));
            float p10 = exp2f(fmaf(sacc[nb][2], c1, -hs2 * s1.x));
            float p11 = exp2f(fmaf(sacc[nb][3], c1, -hs2 * s1.y));
            ls0 += p00 + p01;
            ls1 += p10 + p11;
            uint32_t w0 = pkh2(p00, p01);
            uint32_t w1 = pkh2(p10, p11);
            const int kk2 = nb >> 1;
            if (nb & 1) { pa[kk2][2] = w0; pa[kk2][3] = w1; }
            else        { pa[kk2][0] = w0; pa[kk2][1] = w1; }
        }

        // ---- O += P @ V (single fp16 pass, V via ldmatrix.trans) ----
#pragma unroll
        for (int kk2 = 0; kk2 < 4; kk2++) {
#pragma unroll
            for (int nbp = 0; nbp < 4; nbp++) {
                uint32_t vf[4];
                ldsm4t(vf, aV + kk2 * (16 * RSTR) + nbp * 32);
                mma_f16(oacc[2*nbp],   pa[kk2], vf[0], vf[1]);
                mma_f16(oacc[2*nbp+1], pa[kk2], vf[2], vf[3]);
            }
        }
        __syncthreads();   // all warps done with stage s before restage
    }

    // ---- epilogue: reduce row sums, scale, write split fp16 O ----
    ls0 += __shfl_xor_sync(0xffffffffu, ls0, 1);
    ls0 += __shfl_xor_sync(0xffffffffu, ls0, 2);
    ls1 += __shfl_xor_sync(0xffffffffu, ls1, 1);
    ls1 += __shfl_xor_sync(0xffffffffu, ls1, 2);
    const float i0 = 1.f / ls0;
    const float i1 = 1.f / ls1;

    const size_t base0 = ((size_t)b * Ss + q0) * 256 + h * 32 + tg;
#pragma unroll
    for (int nb = 0; nb < 8; nb++) {
        uint32_t hi, lo;
        splith2(make_float2(oacc[nb][0] * i0, oacc[nb][1] * i0), hi, lo);
        g_Oh16[base0 + nb * 4] = hi;
        g_Ol16[base0 + nb * 4] = lo;
        splith2(make_float2(oacc[nb][2] * i1, oacc[nb][3] * i1), hi, lo);
        g_Oh16[base0 + 8 * 256 + nb * 4] = hi;
        g_Ol16[base0 + 8 * 256 + nb * 4] = lo;
    }
}

// ---------------------------------------------------------------------------
extern "C" void kernel_launch(void* const* d_in, const int* in_sizes, int n_in,
                              void* d_out, int out_size) {
    const float* x     = (const float*)d_in[0];
    const float* shift = (const float*)d_in[1];
    const float* mask  = (const float*)d_in[2];
    const float* W     = (const float*)d_in[3];
    const float* b     = (const float*)d_in[4];
    const float* Wo    = (const float*)d_in[5];
    const float* bo    = (const float*)d_in[6];
    float* out = (float*)d_out;

    cudaFuncSetAttribute(tc_gemm<0>, cudaFuncAttributeMaxDynamicSharedMemorySize,
                         GEMM_SMEM);
    cudaFuncSetAttribute(tc_gemm<1>, cudaFuncAttributeMaxDynamicSharedMemorySize,
                         GEMM_SMEM);
    cudaFuncSetAttribute(attn_kernel, cudaFuncAttributeMaxDynamicSharedMemorySize,
                         ATT_SMEM);

    // fp16 tables: X hi/lo, W, Wo, fused shift/mask
    presplit<<<2048, 256>>>(x, W, Wo, shift, mask);

    // QKV projection: fp16 2-pass, pipelined; emits single fp16 Q/K/V
    tc_gemm<0><<<dim3(12, 32), 256, GEMM_SMEM>>>(b, nullptr);

    // attention: single-pass fp16, pipelined K/V, fused shm table
    attn_kernel<<<dim3(Hh, Ss / 128, Bb), 256, ATT_SMEM>>>();

    // output projection: fp16 2-pass, pipelined
    tc_gemm<1><<<dim3(4, 32), 256, GEMM_SMEM>>>(bo, out);
}